// round 2
// baseline (speedup 1.0000x reference)
#include <cuda_runtime.h>
#include <cuda_bf16.h>
#include <math.h>

// Problem dims (fixed by the reference)
#define BATCH 4
#define SEQ   2048
#define DIM   1024

// Scratch in __device__ globals (no allocation allowed)
__device__ float g_Q[BATCH * SEQ * DIM];
__device__ float g_K[BATCH * SEQ * DIM];
__device__ float g_V[BATCH * SEQ * DIM];
__device__ float g_S[BATCH * SEQ * SEQ];

// ---------------------------------------------------------------------------
// Tiled SGEMM: C[b] = A[b] (MxK, row-major) * op(B[b])
//   BT=true : B is NxK row-major (C = A * B^T)   -- used for X*W^T and Q*K^T
//   BT=false: B is KxN row-major (C = A * B)     -- used for P*V
// BM=BN=128, BK=16, 256 threads, 8x8 per-thread register tile.
// All dims here are multiples of the tile sizes; no bounds checks needed.
// ---------------------------------------------------------------------------
#define BM 128
#define BN 128
#define BK 16
#define TM 8
#define TN 8

template <bool BT>
__global__ __launch_bounds__(256) void sgemm_kernel(
    const float* __restrict__ Ag, const float* __restrict__ Bg,
    float* __restrict__ Cg,
    int M, int N, int K,
    size_t strideA, size_t strideB, size_t strideC)
{
    const float* A = Ag + (size_t)blockIdx.z * strideA;
    const float* B = Bg + (size_t)blockIdx.z * strideB;
    float*       C = Cg + (size_t)blockIdx.z * strideC;

    __shared__ float As[BK][BM];
    __shared__ float Bs[BK][BN];

    const int t  = threadIdx.x;
    const int tm = t >> 4;          // 0..15
    const int tn = t & 15;          // 0..15
    const int m0 = blockIdx.y * BM;
    const int n0 = blockIdx.x * BN;

    float acc[TM][TN];
#pragma unroll
    for (int i = 0; i < TM; i++)
#pragma unroll
        for (int j = 0; j < TN; j++) acc[i][j] = 0.0f;

    for (int k0 = 0; k0 < K; k0 += BK) {
        // ---- load A tile (128 rows x 16 cols), transposed into As[k][m]
#pragma unroll
        for (int r = 0; r < 2; r++) {
            int f   = t + r * 256;      // 0..511 float4 slots
            int row = f >> 2;           // 0..127
            int c4  = f & 3;            // 0..3
            float4 v = *(const float4*)&A[(size_t)(m0 + row) * K + k0 + c4 * 4];
            As[c4 * 4 + 0][row] = v.x;
            As[c4 * 4 + 1][row] = v.y;
            As[c4 * 4 + 2][row] = v.z;
            As[c4 * 4 + 3][row] = v.w;
        }
        // ---- load B tile
        if (BT) {
            // B is NxK row-major: Bs[k][n] = B[n, k]
#pragma unroll
            for (int r = 0; r < 2; r++) {
                int f   = t + r * 256;
                int row = f >> 2;       // n within tile
                int c4  = f & 3;
                float4 v = *(const float4*)&B[(size_t)(n0 + row) * K + k0 + c4 * 4];
                Bs[c4 * 4 + 0][row] = v.x;
                Bs[c4 * 4 + 1][row] = v.y;
                Bs[c4 * 4 + 2][row] = v.z;
                Bs[c4 * 4 + 3][row] = v.w;
            }
        } else {
            // B is KxN row-major: Bs[k][n] = B[k, n] (contiguous along n)
#pragma unroll
            for (int r = 0; r < 2; r++) {
                int f    = t + r * 256;
                int krow = f >> 5;      // 0..15
                int c4   = f & 31;      // 0..31
                float4 v = *(const float4*)&B[(size_t)(k0 + krow) * N + n0 + c4 * 4];
                *(float4*)&Bs[krow][c4 * 4] = v;
            }
        }
        __syncthreads();

#pragma unroll
        for (int kk = 0; kk < BK; kk++) {
            float a[TM], b[TN];
#pragma unroll
            for (int i4 = 0; i4 < TM / 4; i4++)
                *(float4*)&a[i4 * 4] = *(const float4*)&As[kk][tm * TM + i4 * 4];
#pragma unroll
            for (int j4 = 0; j4 < TN / 4; j4++)
                *(float4*)&b[j4 * 4] = *(const float4*)&Bs[kk][tn * TN + j4 * 4];
#pragma unroll
            for (int i = 0; i < TM; i++)
#pragma unroll
                for (int j = 0; j < TN; j++)
                    acc[i][j] = fmaf(a[i], b[j], acc[i][j]);
        }
        __syncthreads();
    }

#pragma unroll
    for (int i = 0; i < TM; i++) {
#pragma unroll
        for (int j4 = 0; j4 < TN / 4; j4++) {
            float4 v = make_float4(acc[i][j4 * 4 + 0], acc[i][j4 * 4 + 1],
                                   acc[i][j4 * 4 + 2], acc[i][j4 * 4 + 3]);
            *(float4*)&C[(size_t)(m0 + tm * TM + i) * N + n0 + tn * TN + j4 * 4] = v;
        }
    }
}

// ---------------------------------------------------------------------------
// Row softmax with pre-scale: row <- softmax(row * scale)
// One block (256 threads) per row of length `cols`.
// ---------------------------------------------------------------------------
__global__ __launch_bounds__(256) void softmax_kernel(float* __restrict__ S,
                                                      int cols, float scale)
{
    float* row = S + (size_t)blockIdx.x * cols;
    const int t = threadIdx.x;
    __shared__ float red[256];

    // max
    float lmax = -INFINITY;
    for (int i = t; i < cols; i += 256) lmax = fmaxf(lmax, row[i] * scale);
    red[t] = lmax;
    __syncthreads();
    for (int s = 128; s > 0; s >>= 1) {
        if (t < s) red[t] = fmaxf(red[t], red[t + s]);
        __syncthreads();
    }
    const float m = red[0];
    __syncthreads();

    // exp + sum
    float lsum = 0.0f;
    for (int i = t; i < cols; i += 256) {
        float e = __expf(row[i] * scale - m);
        row[i] = e;
        lsum += e;
    }
    red[t] = lsum;
    __syncthreads();
    for (int s = 128; s > 0; s >>= 1) {
        if (t < s) red[t] += red[t + s];
        __syncthreads();
    }
    const float inv = 1.0f / red[0];
    __syncthreads();

    for (int i = t; i < cols; i += 256) row[i] *= inv;
}

// ---------------------------------------------------------------------------
// kernel_launch
// Input order (metadata): x, W_key, W_query, W_value. Output: context f32.
// ---------------------------------------------------------------------------
extern "C" void kernel_launch(void* const* d_in, const int* in_sizes, int n_in,
                              void* d_out, int out_size)
{
    const float* x  = (const float*)d_in[0];
    const float* Wk = (const float*)d_in[1];
    const float* Wq = (const float*)d_in[2];
    const float* Wv = (const float*)d_in[3];
    float* out = (float*)d_out;

    float *Q, *K, *V, *S;
    cudaGetSymbolAddress((void**)&Q, g_Q);
    cudaGetSymbolAddress((void**)&K, g_K);
    cudaGetSymbolAddress((void**)&V, g_V);
    cudaGetSymbolAddress((void**)&S, g_S);

    const int M_qkv = BATCH * SEQ;   // 8192

    // 1) QKV projections: [8192,1024] = X[8192,1024] * W^T[1024,1024]
    {
        dim3 grid(DIM / BN, M_qkv / BM, 1);
        sgemm_kernel<true><<<grid, 256>>>(x, Wq, Q, M_qkv, DIM, DIM, 0, 0, 0);
        sgemm_kernel<true><<<grid, 256>>>(x, Wk, K, M_qkv, DIM, DIM, 0, 0, 0);
        sgemm_kernel<true><<<grid, 256>>>(x, Wv, V, M_qkv, DIM, DIM, 0, 0, 0);
    }

    // 2) scores[b] = Q[b] * K[b]^T : [2048,2048] , K = 1024
    {
        dim3 grid(SEQ / BN, SEQ / BM, BATCH);
        sgemm_kernel<true><<<grid, 256>>>(Q, K, S, SEQ, SEQ, DIM,
                                          (size_t)SEQ * DIM, (size_t)SEQ * DIM,
                                          (size_t)SEQ * SEQ);
    }

    // 3) softmax over last dim with scale 1/sqrt(1024) = 1/32
    {
        softmax_kernel<<<BATCH * SEQ, 256>>>(S, SEQ, 1.0f / 32.0f);
    }

    // 4) context[b] = P[b] * V[b] : [2048,1024], K = 2048
    {
        dim3 grid(DIM / BN, SEQ / BM, BATCH);
        sgemm_kernel<false><<<grid, 256>>>(S, V, out, SEQ, DIM, SEQ,
                                           (size_t)SEQ * SEQ, (size_t)SEQ * DIM,
                                           (size_t)SEQ * DIM);
    }
}

// round 4
// speedup vs baseline: 1.7558x; 1.7558x over previous
#include <cuda_runtime.h>
#include <cuda_bf16.h>
#include <math.h>
#include <stdint.h>

#define BATCH 4
#define SEQ   2048
#define DIM   1024
#define MQ    (BATCH * SEQ)      // 8192

// ---------------------------------------------------------------------------
// Device scratch (no allocation allowed)
// ---------------------------------------------------------------------------
__device__ float          g_S[BATCH * SEQ * SEQ];            // fp32 scores
__device__ __nv_bfloat16  g_Xhi[MQ * DIM],  g_Xlo[MQ * DIM];
__device__ __nv_bfloat16  g_Wqhi[DIM * DIM], g_Wqlo[DIM * DIM];
__device__ __nv_bfloat16  g_Wkhi[DIM * DIM], g_Wklo[DIM * DIM];
__device__ __nv_bfloat16  g_Wvhi[DIM * DIM], g_Wvlo[DIM * DIM];
__device__ __nv_bfloat16  g_Qhi[MQ * DIM],  g_Qlo[MQ * DIM];
__device__ __nv_bfloat16  g_Khi[MQ * DIM],  g_Klo[MQ * DIM];
__device__ __nv_bfloat16  g_Vthi[MQ * DIM], g_Vtlo[MQ * DIM];   // [B][D][S]
__device__ __nv_bfloat16  g_Phi[BATCH * SEQ * SEQ], g_Plo[BATCH * SEQ * SEQ];

// ---------------------------------------------------------------------------
// PTX helpers (all sm_80-class ISA: cp.async, ldmatrix, mma.sync)
// ---------------------------------------------------------------------------
__device__ __forceinline__ uint32_t smem_u32(const void* p) {
    uint32_t a;
    asm("{ .reg .u64 t; cvta.to.shared.u64 t, %1; cvt.u32.u64 %0, t; }"
        : "=r"(a) : "l"(p));
    return a;
}

#define CP_ASYNC16(dst, src) \
    asm volatile("cp.async.cg.shared.global [%0], [%1], 16;" :: "r"(dst), "l"(src))
#define CP_COMMIT() asm volatile("cp.async.commit_group;" ::: "memory")
#define CP_WAIT1()  asm volatile("cp.async.wait_group 1;"  ::: "memory")
#define CP_WAIT0()  asm volatile("cp.async.wait_group 0;"  ::: "memory")

#define LDSM_X4(r0, r1, r2, r3, addr) \
    asm volatile("ldmatrix.sync.aligned.m8n8.x4.shared.b16 {%0,%1,%2,%3}, [%4];" \
                 : "=r"(r0), "=r"(r1), "=r"(r2), "=r"(r3) : "r"(addr))
#define LDSM_X2(r0, r1, addr) \
    asm volatile("ldmatrix.sync.aligned.m8n8.x2.shared.b16 {%0,%1}, [%2];" \
                 : "=r"(r0), "=r"(r1) : "r"(addr))

#define MMA16816(d, a, b) \
    asm volatile("mma.sync.aligned.m16n8k16.row.col.f32.bf16.bf16.f32 " \
                 "{%0,%1,%2,%3},{%4,%5,%6,%7},{%8,%9},{%0,%1,%2,%3};" \
                 : "+f"((d)[0]), "+f"((d)[1]), "+f"((d)[2]), "+f"((d)[3]) \
                 : "r"((a)[0]), "r"((a)[1]), "r"((a)[2]), "r"((a)[3]), \
                   "r"((b)[0]), "r"((b)[1]))

#define SWZ(bo) ((bo) ^ (((bo) >> 3) & 0x70))

// ---------------------------------------------------------------------------
// GEMM: C[M,N] = A[M,K]*B[N,K]^T with A,B as bf16 hi/lo pairs (K-major rows).
// 3-pass: Ahi*Bhi + Ahi*Blo + Alo*Bhi, fp32 accumulate.
// CTA tile 128x128, BK=32, 8 warps (warp tile 64x32), 3-stage cp.async pipe.
// SMEM tile row layout: 128 bytes = [hi 32 bf16 | lo 32 bf16], SW128 swizzle.
// EPI: 0=fp32 C; 1=hi/lo bf16 of acc*escale; 2=transpose hi/lo (V->Vt[B][D][S])
// ---------------------------------------------------------------------------
#define STAGES    3
#define TILE_HB   16384                  // one operand tile: 128 rows * 128B
#define STAGE_B   (2 * TILE_HB)          // A + B
#define GSMEM     (STAGES * STAGE_B)     // 96 KB

__device__ __forceinline__ void issue_stage_load(
    uint32_t tile_u,
    const __nv_bfloat16* __restrict__ Ahi, const __nv_bfloat16* __restrict__ Alo,
    const __nv_bfloat16* __restrict__ Bhi, const __nv_bfloat16* __restrict__ Blo,
    int m0, int n0, int K, int kc, int t)
{
    const int r  = t >> 1;               // 0..127 (row handled by this thread pair)
    const int h  = t & 1;                // half selector: 0 -> chunks 0..3, 1 -> 4..7
    // A tile: 4 chunks of 16B for this thread
#pragma unroll
    for (int c = 0; c < 4; c++) {
        int c8 = h * 4 + c;              // 0..7
        const __nv_bfloat16* src = (c8 < 4 ? Ahi : Alo);
        const __nv_bfloat16* s = src + (size_t)(m0 + r) * K + kc * 32 + (c8 & 3) * 8;
        uint32_t dst = tile_u + SWZ((uint32_t)(r * 128 + c8 * 16));
        CP_ASYNC16(dst, s);
    }
    // B tile
#pragma unroll
    for (int c = 0; c < 4; c++) {
        int c8 = h * 4 + c;
        const __nv_bfloat16* src = (c8 < 4 ? Bhi : Blo);
        const __nv_bfloat16* s = src + (size_t)(n0 + r) * K + kc * 32 + (c8 & 3) * 8;
        uint32_t dst = tile_u + TILE_HB + SWZ((uint32_t)(r * 128 + c8 * 16));
        CP_ASYNC16(dst, s);
    }
}

template <int EPI>
__global__ __launch_bounds__(256, 2) void gemm_mma3(
    const __nv_bfloat16* __restrict__ Ahi, const __nv_bfloat16* __restrict__ Alo,
    const __nv_bfloat16* __restrict__ Bhi, const __nv_bfloat16* __restrict__ Blo,
    float* __restrict__ Cf, __nv_bfloat16* __restrict__ Chi,
    __nv_bfloat16* __restrict__ Clo,
    int M, int N, int K,
    size_t sA, size_t sB, size_t sC, float escale)
{
    extern __shared__ char smem[];
    const uint32_t sb = smem_u32(smem);
    const int t     = threadIdx.x;
    const int wid   = t >> 5;
    const int lane  = t & 31;
    const int warpm = wid >> 2;          // 0..1
    const int warpn = wid & 3;           // 0..3
    const int m0    = blockIdx.y * 128;
    const int n0    = blockIdx.x * 128;
    const size_t zb = blockIdx.z;

    Ahi += zb * sA;  Alo += zb * sA;
    Bhi += zb * sB;  Blo += zb * sB;

    float acc[4][4][4];
#pragma unroll
    for (int i = 0; i < 4; i++)
#pragma unroll
        for (int j = 0; j < 4; j++)
#pragma unroll
            for (int c = 0; c < 4; c++) acc[i][j][c] = 0.0f;

    const int nch = K / 32;

    // prologue: prefetch 2 stages
    issue_stage_load(sb + 0 * STAGE_B, Ahi, Alo, Bhi, Blo, m0, n0, K, 0, t);
    CP_COMMIT();
    issue_stage_load(sb + 1 * STAGE_B, Ahi, Alo, Bhi, Blo, m0, n0, K, 1, t);
    CP_COMMIT();

    // per-lane invariant address pieces
    const uint32_t a_row  = (uint32_t)(warpm * 64 + (lane & 15));   // + mt*16
    const uint32_t a_k16b = ((lane >> 4) & 1) * 16;
    const uint32_t b_row  = (uint32_t)(warpn * 32 + (lane & 7));    // + nt*8
    const uint32_t b_k16b = ((lane >> 3) & 1) * 16;

    for (int kc = 0; kc < nch; kc++) {
        CP_WAIT1();
        __syncthreads();

        const uint32_t tu = sb + (kc % STAGES) * STAGE_B;

#pragma unroll
        for (int k16 = 0; k16 < 2; k16++) {
            uint32_t a[4][4], bh[4][2], bl[4][2];
            // A hi fragments
#pragma unroll
            for (int mt = 0; mt < 4; mt++) {
                uint32_t bo = (a_row + mt * 16) * 128 + 0 + k16 * 32 + a_k16b;
                LDSM_X4(a[mt][0], a[mt][1], a[mt][2], a[mt][3], tu + SWZ(bo));
            }
            // B hi + lo fragments
#pragma unroll
            for (int nt = 0; nt < 4; nt++) {
                uint32_t boh = (b_row + nt * 8) * 128 + 0  + k16 * 32 + b_k16b;
                uint32_t bol = (b_row + nt * 8) * 128 + 64 + k16 * 32 + b_k16b;
                LDSM_X2(bh[nt][0], bh[nt][1], tu + TILE_HB + SWZ(boh));
                LDSM_X2(bl[nt][0], bl[nt][1], tu + TILE_HB + SWZ(bol));
            }
            // HH + HL
#pragma unroll
            for (int mt = 0; mt < 4; mt++)
#pragma unroll
                for (int nt = 0; nt < 4; nt++) MMA16816(acc[mt][nt], a[mt], bh[nt]);
#pragma unroll
            for (int mt = 0; mt < 4; mt++)
#pragma unroll
                for (int nt = 0; nt < 4; nt++) MMA16816(acc[mt][nt], a[mt], bl[nt]);
            // A lo fragments (reuse regs) + LH
#pragma unroll
            for (int mt = 0; mt < 4; mt++) {
                uint32_t bo = (a_row + mt * 16) * 128 + 64 + k16 * 32 + a_k16b;
                LDSM_X4(a[mt][0], a[mt][1], a[mt][2], a[mt][3], tu + SWZ(bo));
            }
#pragma unroll
            for (int mt = 0; mt < 4; mt++)
#pragma unroll
                for (int nt = 0; nt < 4; nt++) MMA16816(acc[mt][nt], a[mt], bh[nt]);
        }

        __syncthreads();
        if (kc + 2 < nch) {
            issue_stage_load(sb + ((kc + 2) % STAGES) * STAGE_B,
                             Ahi, Alo, Bhi, Blo, m0, n0, K, kc + 2, t);
        }
        CP_COMMIT();   // keep group count in lockstep even on tail
    }
    CP_WAIT0();

    // ---- epilogue straight from registers ----
    const int rbase = lane >> 2;           // 0..7
    const int cbase = (lane & 3) * 2;

#pragma unroll
    for (int mt = 0; mt < 4; mt++) {
#pragma unroll
        for (int nt = 0; nt < 4; nt++) {
            int row = m0 + warpm * 64 + mt * 16 + rbase;
            int col = n0 + warpn * 32 + nt * 8 + cbase;
            float* d = acc[mt][nt];
            if (EPI == 0) {
                float* Cb = Cf + zb * sC;
                *(float2*)&Cb[(size_t)row * N + col]       = make_float2(d[0], d[1]);
                *(float2*)&Cb[(size_t)(row + 8) * N + col] = make_float2(d[2], d[3]);
            } else if (EPI == 1) {
#pragma unroll
                for (int hrow = 0; hrow < 2; hrow++) {
                    float a0 = d[hrow * 2 + 0] * escale;
                    float a1 = d[hrow * 2 + 1] * escale;
                    __nv_bfloat16 h0 = __float2bfloat16(a0);
                    __nv_bfloat16 h1 = __float2bfloat16(a1);
                    __nv_bfloat16 l0 = __float2bfloat16(a0 - __bfloat162float(h0));
                    __nv_bfloat16 l1 = __float2bfloat16(a1 - __bfloat162float(h1));
                    size_t idx = (size_t)(row + hrow * 8) * N + col;
                    uint32_t hp = (uint32_t)__bfloat16_as_ushort(h0) |
                                  ((uint32_t)__bfloat16_as_ushort(h1) << 16);
                    uint32_t lp = (uint32_t)__bfloat16_as_ushort(l0) |
                                  ((uint32_t)__bfloat16_as_ushort(l1) << 16);
                    *(uint32_t*)&Chi[idx] = hp;
                    *(uint32_t*)&Clo[idx] = lp;
                }
            } else {   // EPI == 2 : V transpose  out[(b*DIM + n)*SEQ + s]
#pragma unroll
                for (int hrow = 0; hrow < 2; hrow++) {
#pragma unroll
                    for (int cc = 0; cc < 2; cc++) {
                        int m = row + hrow * 8;
                        int b = m >> 11, s = m & 2047;
                        int n = col + cc;
                        float v = d[hrow * 2 + cc] * escale;
                        __nv_bfloat16 h = __float2bfloat16(v);
                        __nv_bfloat16 l = __float2bfloat16(v - __bfloat162float(h));
                        size_t oi = ((size_t)(b * DIM + n)) * SEQ + s;
                        Chi[oi] = h;
                        Clo[oi] = l;
                    }
                }
            }
        }
    }
}

// ---------------------------------------------------------------------------
// fp32 -> bf16 hi/lo split (vectorized by 4)
// ---------------------------------------------------------------------------
__global__ __launch_bounds__(256) void split_kernel(
    const float* __restrict__ src, __nv_bfloat16* __restrict__ hi,
    __nv_bfloat16* __restrict__ lo, int n4)
{
    int i = blockIdx.x * blockDim.x + threadIdx.x;
    if (i >= n4) return;
    float4 x = ((const float4*)src)[i];
    float a[4] = {x.x, x.y, x.z, x.w};
    uint32_t hp[2], lp[2];
#pragma unroll
    for (int j = 0; j < 2; j++) {
        __nv_bfloat16 h0 = __float2bfloat16(a[j * 2 + 0]);
        __nv_bfloat16 h1 = __float2bfloat16(a[j * 2 + 1]);
        __nv_bfloat16 l0 = __float2bfloat16(a[j * 2 + 0] - __bfloat162float(h0));
        __nv_bfloat16 l1 = __float2bfloat16(a[j * 2 + 1] - __bfloat162float(h1));
        hp[j] = (uint32_t)__bfloat16_as_ushort(h0) | ((uint32_t)__bfloat16_as_ushort(h1) << 16);
        lp[j] = (uint32_t)__bfloat16_as_ushort(l0) | ((uint32_t)__bfloat16_as_ushort(l1) << 16);
    }
    ((uint2*)hi)[i] = make_uint2(hp[0], hp[1]);
    ((uint2*)lo)[i] = make_uint2(lp[0], lp[1]);
}

// ---------------------------------------------------------------------------
// Softmax over rows of S (pre-scaled via Q), writes P hi/lo bf16.
// One block (256 threads) per row of 2048.
// ---------------------------------------------------------------------------
__global__ __launch_bounds__(256) void softmax_split_kernel(
    const float* __restrict__ S, __nv_bfloat16* __restrict__ Phi,
    __nv_bfloat16* __restrict__ Plo)
{
    const float* row = S + (size_t)blockIdx.x * SEQ;
    __nv_bfloat16* ph = Phi + (size_t)blockIdx.x * SEQ;
    __nv_bfloat16* pl = Plo + (size_t)blockIdx.x * SEQ;
    const int t = threadIdx.x;
    __shared__ float red[256];

    float v[8];
#pragma unroll
    for (int i = 0; i < 8; i++) v[i] = row[t + i * 256];

    float lmax = v[0];
#pragma unroll
    for (int i = 1; i < 8; i++) lmax = fmaxf(lmax, v[i]);
    red[t] = lmax;
    __syncthreads();
    for (int s = 128; s > 0; s >>= 1) {
        if (t < s) red[t] = fmaxf(red[t], red[t + s]);
        __syncthreads();
    }
    const float m = red[0];
    __syncthreads();

    float lsum = 0.0f;
#pragma unroll
    for (int i = 0; i < 8; i++) { v[i] = __expf(v[i] - m); lsum += v[i]; }
    red[t] = lsum;
    __syncthreads();
    for (int s = 128; s > 0; s >>= 1) {
        if (t < s) red[t] += red[t + s];
        __syncthreads();
    }
    const float inv = 1.0f / red[0];

#pragma unroll
    for (int i = 0; i < 8; i++) {
        float p = v[i] * inv;
        __nv_bfloat16 h = __float2bfloat16(p);
        ph[t + i * 256] = h;
        pl[t + i * 256] = __float2bfloat16(p - __bfloat162float(h));
    }
}

// ---------------------------------------------------------------------------
// kernel_launch : x, W_key, W_query, W_value -> context (fp32)
// ---------------------------------------------------------------------------
extern "C" void kernel_launch(void* const* d_in, const int* in_sizes, int n_in,
                              void* d_out, int out_size)
{
    const float* x  = (const float*)d_in[0];
    const float* Wk = (const float*)d_in[1];
    const float* Wq = (const float*)d_in[2];
    const float* Wv = (const float*)d_in[3];
    float* out = (float*)d_out;

    float* S;
    __nv_bfloat16 *Xhi, *Xlo, *Wqhi, *Wqlo, *Wkhi, *Wklo, *Wvhi, *Wvlo;
    __nv_bfloat16 *Qhi, *Qlo, *Khi, *Klo, *Vthi, *Vtlo, *Phi, *Plo;
    cudaGetSymbolAddress((void**)&S,    g_S);
    cudaGetSymbolAddress((void**)&Xhi,  g_Xhi);  cudaGetSymbolAddress((void**)&Xlo,  g_Xlo);
    cudaGetSymbolAddress((void**)&Wqhi, g_Wqhi); cudaGetSymbolAddress((void**)&Wqlo, g_Wqlo);
    cudaGetSymbolAddress((void**)&Wkhi, g_Wkhi); cudaGetSymbolAddress((void**)&Wklo, g_Wklo);
    cudaGetSymbolAddress((void**)&Wvhi, g_Wvhi); cudaGetSymbolAddress((void**)&Wvlo, g_Wvlo);
    cudaGetSymbolAddress((void**)&Qhi,  g_Qhi);  cudaGetSymbolAddress((void**)&Qlo,  g_Qlo);
    cudaGetSymbolAddress((void**)&Khi,  g_Khi);  cudaGetSymbolAddress((void**)&Klo,  g_Klo);
    cudaGetSymbolAddress((void**)&Vthi, g_Vthi); cudaGetSymbolAddress((void**)&Vtlo, g_Vtlo);
    cudaGetSymbolAddress((void**)&Phi,  g_Phi);  cudaGetSymbolAddress((void**)&Plo,  g_Plo);

    cudaFuncSetAttribute(gemm_mma3<0>, cudaFuncAttributeMaxDynamicSharedMemorySize, GSMEM);
    cudaFuncSetAttribute(gemm_mma3<1>, cudaFuncAttributeMaxDynamicSharedMemorySize, GSMEM);
    cudaFuncSetAttribute(gemm_mma3<2>, cudaFuncAttributeMaxDynamicSharedMemorySize, GSMEM);

    // 1) split inputs into bf16 hi/lo
    split_kernel<<<(MQ * DIM / 4 + 255) / 256, 256>>>(x,  Xhi,  Xlo,  MQ * DIM / 4);
    split_kernel<<<(DIM * DIM / 4 + 255) / 256, 256>>>(Wq, Wqhi, Wqlo, DIM * DIM / 4);
    split_kernel<<<(DIM * DIM / 4 + 255) / 256, 256>>>(Wk, Wkhi, Wklo, DIM * DIM / 4);
    split_kernel<<<(DIM * DIM / 4 + 255) / 256, 256>>>(Wv, Wvhi, Wvlo, DIM * DIM / 4);

    // 2) projections: Q (scaled by 1/32, split), K (split), V (transpose-split)
    {
        dim3 grid(DIM / 128, MQ / 128, 1);
        gemm_mma3<1><<<grid, 256, GSMEM>>>(Xhi, Xlo, Wqhi, Wqlo,
            nullptr, Qhi, Qlo, MQ, DIM, DIM, 0, 0, 0, 1.0f / 32.0f);
        gemm_mma3<1><<<grid, 256, GSMEM>>>(Xhi, Xlo, Wkhi, Wklo,
            nullptr, Khi, Klo, MQ, DIM, DIM, 0, 0, 0, 1.0f);
        gemm_mma3<2><<<grid, 256, GSMEM>>>(Xhi, Xlo, Wvhi, Wvlo,
            nullptr, Vthi, Vtlo, MQ, DIM, DIM, 0, 0, 0, 1.0f);
    }

    // 3) scores[b] = Qs[b] * K[b]^T  (already scaled) -> fp32 S
    {
        dim3 grid(SEQ / 128, SEQ / 128, BATCH);
        gemm_mma3<0><<<grid, 256, GSMEM>>>(Qhi, Qlo, Khi, Klo,
            S, nullptr, nullptr, SEQ, SEQ, DIM,
            (size_t)SEQ * DIM, (size_t)SEQ * DIM, (size_t)SEQ * SEQ, 1.0f);
    }

    // 4) softmax rows -> P hi/lo bf16
    softmax_split_kernel<<<BATCH * SEQ, 256>>>(S, Phi, Plo);

    // 5) context[b] = P[b] * Vt[b]^T -> out fp32
    {
        dim3 grid(DIM / 128, SEQ / 128, BATCH);
        gemm_mma3<0><<<grid, 256, GSMEM>>>(Phi, Plo, Vthi, Vtlo,
            out, nullptr, nullptr, SEQ, DIM, SEQ,
            (size_t)SEQ * SEQ, (size_t)DIM * SEQ, (size_t)SEQ * DIM, 1.0f);
    }
}